// round 1
// baseline (speedup 1.0000x reference)
#include <cuda_runtime.h>
#include <math.h>

#define B_   16
#define N_   32768
#define S_   256
#define H_   256
#define NH_  8
#define DH_  32
#define DFF_ 1024
#define NC_  13

// ---------------- scratch (device globals; no allocations allowed) ----------
__device__ float g_sumxyz[B_*S_*3];
__device__ float g_sumfeat[B_*S_*4];
__device__ float g_cnt[B_*S_];
__device__ int   g_assign[B_*N_];
__device__ float g_x[B_*S_*H_];
__device__ float g_qkv[B_*S_*3*H_];
__device__ float g_attn[B_*S_*H_];
__device__ float g_tmp[B_*S_*H_];
__device__ float g_ff[B_*S_*DFF_];
__device__ float g_h1[B_*S_*H_];
__device__ float g_logits[B_*S_*NC_];

// ---------------- utils ----------
__device__ __forceinline__ float gelu_exact(float x) {
    return 0.5f * x * (1.0f + erff(x * 0.70710678118654752440f));
}

// ---------------- zero the segment accumulators ----------
__global__ void zero_kernel() {
    int t = blockIdx.x * blockDim.x + threadIdx.x;
    if (t < B_*S_*3) g_sumxyz[t]  = 0.f;
    if (t < B_*S_*4) g_sumfeat[t] = 0.f;
    if (t < B_*S_)   g_cnt[t]     = 0.f;
}

// ---------------- point -> seed argmin + block-local segment sums ----------
// grid: B_*16 blocks (2048 points/block), 256 threads
__global__ void assign_kernel(const float* __restrict__ xyz,
                              const float* __restrict__ feat,
                              const int*   __restrict__ seed_idx) {
    __shared__ float s_sx[S_], s_sy[S_], s_sz[S_], s_s2[S_];
    __shared__ float s_acc[S_*8];
    int b     = blockIdx.x >> 4;
    int chunk = blockIdx.x & 15;
    int tid   = threadIdx.x;

    {
        int idx = seed_idx[tid];
        float a0 = xyz[(size_t)(b*N_ + idx)*3 + 0];
        float a1 = xyz[(size_t)(b*N_ + idx)*3 + 1];
        float a2 = xyz[(size_t)(b*N_ + idx)*3 + 2];
        s_sx[tid] = a0; s_sy[tid] = a1; s_sz[tid] = a2;
        s_s2[tid] = (a0*a0 + a1*a1) + a2*a2;
    }
    #pragma unroll
    for (int i = 0; i < 8; i++) s_acc[tid + i*256] = 0.f;
    __syncthreads();

    for (int p = 0; p < 8; p++) {
        int n = chunk*2048 + p*256 + tid;
        size_t off = (size_t)(b*N_ + n);
        float x0 = xyz[off*3+0], x1 = xyz[off*3+1], x2 = xyz[off*3+2];
        float x2s = (x0*x0 + x1*x1) + x2*x2;
        float best = INFINITY; int bi = 0;
        for (int s = 0; s < S_; s++) {
            float d = x0 * s_sx[s];
            d = fmaf(x1, s_sy[s], d);
            d = fmaf(x2, s_sz[s], d);
            float d2 = (x2s + s_s2[s]) - 2.0f*d;
            if (d2 < best) { best = d2; bi = s; }   // strict '<': first index wins
        }
        g_assign[off] = bi;
        float4 f = ((const float4*)feat)[off];
        float* a = &s_acc[bi*8];
        atomicAdd(a+0, x0);  atomicAdd(a+1, x1);  atomicAdd(a+2, x2);
        atomicAdd(a+3, f.x); atomicAdd(a+4, f.y); atomicAdd(a+5, f.z); atomicAdd(a+6, f.w);
        atomicAdd(a+7, 1.0f);
    }
    __syncthreads();

    int s  = tid;
    int bs = b*S_ + s;
    atomicAdd(&g_sumxyz [bs*3+0], s_acc[s*8+0]);
    atomicAdd(&g_sumxyz [bs*3+1], s_acc[s*8+1]);
    atomicAdd(&g_sumxyz [bs*3+2], s_acc[s*8+2]);
    atomicAdd(&g_sumfeat[bs*4+0], s_acc[s*8+3]);
    atomicAdd(&g_sumfeat[bs*4+1], s_acc[s*8+4]);
    atomicAdd(&g_sumfeat[bs*4+2], s_acc[s*8+5]);
    atomicAdd(&g_sumfeat[bs*4+3], s_acc[s*8+6]);
    atomicAdd(&g_cnt[bs],         s_acc[s*8+7]);
}

// ---------------- superpoint features -> token projection ----------
// grid: B_*S_ blocks, 256 threads (one per output channel)
__global__ void tokens_kernel(const float* __restrict__ xyz,
                              const int*   __restrict__ seed_idx,
                              const float* __restrict__ pw,
                              const float* __restrict__ pb) {
    __shared__ float sp[7];
    int bs  = blockIdx.x;
    int b   = bs >> 8, s = bs & 255;
    int tid = threadIdx.x;
    if (tid == 0) {
        float cnt   = g_cnt[bs];
        float denom = fmaxf(cnt, 1.0f);
        bool  empty = (cnt == 0.0f);
        int   idx   = seed_idx[s];
        #pragma unroll
        for (int c = 0; c < 3; c++) {
            float seedc = xyz[(size_t)(b*N_ + idx)*3 + c];
            sp[c] = empty ? seedc : g_sumxyz[bs*3+c] / denom;
        }
        #pragma unroll
        for (int c = 0; c < 4; c++)
            sp[3+c] = empty ? 0.f : g_sumfeat[bs*4+c] / denom;
    }
    __syncthreads();
    float acc = 0.f;
    #pragma unroll
    for (int i = 0; i < 7; i++) acc = fmaf(sp[i], pw[tid*7 + i], acc);
    g_x[(size_t)bs*H_ + tid] = acc + pb[tid];
}

// ---------------- generic SGEMM: C = epi(A(MxK) @ W(NxK)^T + bias [+ res]) --
// EPI: 0 = none, 1 = gelu, 2 = +residual
template<int EPI>
__global__ void sgemm(const float* __restrict__ A, const float* __restrict__ W,
                      const float* __restrict__ bias, const float* __restrict__ res,
                      float* __restrict__ C, int M, int N, int K) {
    __shared__ float As[16][68];
    __shared__ float Ws[16][68];
    int tid = threadIdx.x;
    int tx = tid & 15, ty = tid >> 4;
    int bm = blockIdx.y * 64, bn = blockIdx.x * 64;
    int lr = tid >> 2;
    int lc = (tid & 3) << 2;
    float acc[4][4] = {{0.f}};
    const float* Ap = A + (size_t)(bm + lr)*K + lc;
    const float* Wp = W + (size_t)(bn + lr)*K + lc;

    for (int k0 = 0; k0 < K; k0 += 16) {
        float4 a = *(const float4*)(Ap + k0);
        float4 w = *(const float4*)(Wp + k0);
        As[lc+0][lr] = a.x; As[lc+1][lr] = a.y; As[lc+2][lr] = a.z; As[lc+3][lr] = a.w;
        Ws[lc+0][lr] = w.x; Ws[lc+1][lr] = w.y; Ws[lc+2][lr] = w.z; Ws[lc+3][lr] = w.w;
        __syncthreads();
        #pragma unroll
        for (int k = 0; k < 16; k++) {
            float ar[4], br[4];
            #pragma unroll
            for (int i = 0; i < 4; i++) ar[i] = As[k][ty + 16*i];
            #pragma unroll
            for (int j = 0; j < 4; j++) br[j] = Ws[k][tx + 16*j];
            #pragma unroll
            for (int i = 0; i < 4; i++)
                #pragma unroll
                for (int j = 0; j < 4; j++)
                    acc[i][j] = fmaf(ar[i], br[j], acc[i][j]);
        }
        __syncthreads();
    }
    #pragma unroll
    for (int i = 0; i < 4; i++) {
        int mrow = bm + ty + 16*i;
        #pragma unroll
        for (int j = 0; j < 4; j++) {
            int ncol = bn + tx + 16*j;
            float c = acc[i][j] + bias[ncol];
            if (EPI == 1) c = gelu_exact(c);
            if (EPI == 2) c += res[(size_t)mrow*N + ncol];
            C[(size_t)mrow*N + ncol] = c;
        }
    }
}

// ---------------- attention: one block per (b, head), thread = query row ----
__global__ void attention_kernel(const float* __restrict__ qkv,
                                 float* __restrict__ outp) {
    __shared__ float Ks[S_][DH_];
    int bh  = blockIdx.x;
    int b   = bh >> 3, h = bh & 7;
    int tid = threadIdx.x;
    const float* base = qkv + (size_t)b*S_*(3*H_);
    {
        const float4* kr = (const float4*)(base + (size_t)tid*(3*H_) + H_ + h*DH_);
        float4* dst = (float4*)&Ks[tid][0];
        #pragma unroll
        for (int i = 0; i < DH_/4; i++) dst[i] = kr[i];
    }
    float q[DH_];
    {
        const float4* qr = (const float4*)(base + (size_t)tid*(3*H_) + h*DH_);
        #pragma unroll
        for (int i = 0; i < DH_/4; i++) ((float4*)q)[i] = qr[i];
    }
    __syncthreads();

    const float scale = 0.17677669529663688110f;   // 1/sqrt(32)
    float m = -INFINITY, l = 0.f;
    float acc[DH_];
    #pragma unroll
    for (int d = 0; d < DH_; d++) acc[d] = 0.f;
    const float* vbase = base + 2*H_ + h*DH_;

    for (int j = 0; j < S_; j++) {
        float s = 0.f;
        #pragma unroll
        for (int d = 0; d < DH_; d++) s = fmaf(q[d], Ks[j][d], s);
        s *= scale;
        float mn = fmaxf(m, s);
        float c  = expf(m - mn);
        float p  = expf(s - mn);
        l = l*c + p;
        const float4* vr = (const float4*)(vbase + (size_t)j*(3*H_));
        #pragma unroll
        for (int i = 0; i < DH_/4; i++) {
            float4 vv = vr[i];
            acc[i*4+0] = fmaf(acc[i*4+0], c, p*vv.x);
            acc[i*4+1] = fmaf(acc[i*4+1], c, p*vv.y);
            acc[i*4+2] = fmaf(acc[i*4+2], c, p*vv.z);
            acc[i*4+3] = fmaf(acc[i*4+3], c, p*vv.w);
        }
        m = mn;
    }
    float inv = 1.0f / l;
    float* orow = outp + (size_t)(b*S_ + tid)*H_ + h*DH_;
    #pragma unroll
    for (int d = 0; d < DH_; d++) orow[d] = acc[d]*inv;
}

// ---------------- layernorm: one block (256 threads) per row ----------
__global__ void layernorm_kernel(const float* __restrict__ in,
                                 const float* __restrict__ gw,
                                 const float* __restrict__ gb,
                                 float* __restrict__ outp) {
    __shared__ float red[8];
    __shared__ float s_mean, s_var;
    int row = blockIdx.x, tid = threadIdx.x;
    float v = in[(size_t)row*H_ + tid];
    float s = v;
    #pragma unroll
    for (int o = 16; o > 0; o >>= 1) s += __shfl_xor_sync(0xffffffffu, s, o);
    if ((tid & 31) == 0) red[tid >> 5] = s;
    __syncthreads();
    if (tid == 0) {
        float t = 0.f;
        #pragma unroll
        for (int i = 0; i < 8; i++) t += red[i];
        s_mean = t * (1.0f/H_);
    }
    __syncthreads();
    float mean = s_mean;
    float d = v - mean;
    s = d*d;
    #pragma unroll
    for (int o = 16; o > 0; o >>= 1) s += __shfl_xor_sync(0xffffffffu, s, o);
    if ((tid & 31) == 0) red[tid >> 5] = s;
    __syncthreads();
    if (tid == 0) {
        float t = 0.f;
        #pragma unroll
        for (int i = 0; i < 8; i++) t += red[i];
        s_var = t * (1.0f/H_);
    }
    __syncthreads();
    outp[(size_t)row*H_ + tid] = d * rsqrtf(s_var + 1e-5f) * gw[tid] + gb[tid];
}

// ---------------- head2: logits (M x 13), one thread per output ----------
__global__ void head2_kernel(const float* __restrict__ X,
                             const float* __restrict__ W,
                             const float* __restrict__ bias) {
    int t = blockIdx.x * blockDim.x + threadIdx.x;
    if (t >= B_*S_*NC_) return;
    int row = t / NC_, c = t - row*NC_;
    const float4* x = (const float4*)(X + (size_t)row*H_);
    const float4* w = (const float4*)(W + (size_t)c*H_);
    float s0 = 0.f, s1 = 0.f, s2 = 0.f, s3 = 0.f;
    #pragma unroll 8
    for (int k = 0; k < H_/4; k++) {
        float4 xv = x[k], wv = w[k];
        s0 = fmaf(xv.x, wv.x, s0); s1 = fmaf(xv.y, wv.y, s1);
        s2 = fmaf(xv.z, wv.z, s2); s3 = fmaf(xv.w, wv.w, s3);
    }
    g_logits[t] = (s0+s1) + (s2+s3) + bias[c];
}

// ---------------- final gather to point logits ----------
__global__ void gather_kernel(float* __restrict__ out) {
    int t = blockIdx.x * blockDim.x + threadIdx.x;
    if (t >= B_*N_*NC_) return;
    int r = t / NC_;
    int c = t - r*NC_;
    int b = r >> 15;                // r / N_
    int a = g_assign[r];
    out[t] = g_logits[(b*S_ + a)*NC_ + c];
}

// ---------------- host launcher ----------
extern "C" void kernel_launch(void* const* d_in, const int* in_sizes, int n_in,
                              void* d_out, int out_size) {
    const float* xyz      = (const float*)d_in[0];
    const float* feat     = (const float*)d_in[1];
    const int*   seed_idx = (const int*)  d_in[2];
    const float* proj_w   = (const float*)d_in[3];
    const float* proj_b   = (const float*)d_in[4];
    const float* qkv_w    = (const float*)d_in[5];
    const float* qkv_b    = (const float*)d_in[6];
    const float* out_w    = (const float*)d_in[7];
    const float* out_b    = (const float*)d_in[8];
    const float* ln1_g    = (const float*)d_in[9];
    const float* ln1_b    = (const float*)d_in[10];
    const float* ln2_g    = (const float*)d_in[11];
    const float* ln2_b    = (const float*)d_in[12];
    const float* ff1_w    = (const float*)d_in[13];
    const float* ff1_b    = (const float*)d_in[14];
    const float* ff2_w    = (const float*)d_in[15];
    const float* ff2_b    = (const float*)d_in[16];
    const float* hln_g    = (const float*)d_in[17];
    const float* hln_b    = (const float*)d_in[18];
    const float* h1_w     = (const float*)d_in[19];
    const float* h1_b     = (const float*)d_in[20];
    const float* h2_w     = (const float*)d_in[21];
    const float* h2_b     = (const float*)d_in[22];
    float* out = (float*)d_out;

    float *p_x, *p_qkv, *p_attn, *p_tmp, *p_ff, *p_h1;
    cudaGetSymbolAddress((void**)&p_x,    g_x);
    cudaGetSymbolAddress((void**)&p_qkv,  g_qkv);
    cudaGetSymbolAddress((void**)&p_attn, g_attn);
    cudaGetSymbolAddress((void**)&p_tmp,  g_tmp);
    cudaGetSymbolAddress((void**)&p_ff,   g_ff);
    cudaGetSymbolAddress((void**)&p_h1,   g_h1);

    const int M = B_*S_;   // 4096

    zero_kernel<<<(B_*S_*4 + 255)/256, 256>>>();
    assign_kernel<<<B_*16, 256>>>(xyz, feat, seed_idx);
    tokens_kernel<<<B_*S_, 256>>>(xyz, seed_idx, proj_w, proj_b);

    for (int l = 0; l < 2; l++) {
        sgemm<0><<<dim3(3*H_/64, M/64), 256>>>(p_x, qkv_w + (size_t)l*3*H_*H_,
                                               qkv_b + l*3*H_, nullptr, p_qkv,
                                               M, 3*H_, H_);
        attention_kernel<<<B_*NH_, 256>>>(p_qkv, p_attn);
        sgemm<2><<<dim3(H_/64, M/64), 256>>>(p_attn, out_w + (size_t)l*H_*H_,
                                             out_b + l*H_, p_x, p_tmp,
                                             M, H_, H_);
        layernorm_kernel<<<M, 256>>>(p_tmp, ln1_g + l*H_, ln1_b + l*H_, p_x);
        sgemm<1><<<dim3(DFF_/64, M/64), 256>>>(p_x, ff1_w + (size_t)l*DFF_*H_,
                                               ff1_b + l*DFF_, nullptr, p_ff,
                                               M, DFF_, H_);
        sgemm<2><<<dim3(H_/64, M/64), 256>>>(p_ff, ff2_w + (size_t)l*H_*DFF_,
                                             ff2_b + l*H_, p_x, p_tmp,
                                             M, H_, DFF_);
        layernorm_kernel<<<M, 256>>>(p_tmp, ln2_g + l*H_, ln2_b + l*H_, p_x);
    }

    layernorm_kernel<<<M, 256>>>(p_x, hln_g, hln_b, p_tmp);
    sgemm<1><<<dim3(H_/64, M/64), 256>>>(p_tmp, h1_w, h1_b, nullptr, p_h1,
                                         M, H_, H_);
    head2_kernel<<<(M*NC_ + 255)/256, 256>>>(p_h1, h2_w, h2_b);
    gather_kernel<<<(B_*N_*NC_ + 255)/256, 256>>>(out);
}

// round 2
// speedup vs baseline: 1.1135x; 1.1135x over previous
#include <cuda_runtime.h>
#include <math.h>

#define B_   16
#define N_   32768
#define S_   256
#define H_   256
#define NH_  8
#define DH_  32
#define DFF_ 1024
#define NC_  13

// ---------------- scratch (device globals; no allocations allowed) ----------
__device__ float g_sumxyz[B_*S_*3];
__device__ float g_sumfeat[B_*S_*4];
__device__ float g_cnt[B_*S_];
__device__ int   g_assign[B_*N_];
__device__ float g_x[B_*S_*H_];
__device__ float g_qkv[B_*S_*3*H_];
__device__ float g_attn[B_*S_*H_];
__device__ float g_tmp[B_*S_*H_];
__device__ float g_ff[B_*S_*DFF_];
__device__ float g_h1[B_*S_*H_];
__device__ float g_logits[B_*S_*NC_];

// ---------------- utils ----------
__device__ __forceinline__ float gelu_exact(float x) {
    return 0.5f * x * (1.0f + erff(x * 0.70710678118654752440f));
}

// ---------------- zero the segment accumulators ----------
__global__ void zero_kernel() {
    int t = blockIdx.x * blockDim.x + threadIdx.x;
    if (t < B_*S_*3) g_sumxyz[t]  = 0.f;
    if (t < B_*S_*4) g_sumfeat[t] = 0.f;
    if (t < B_*S_)   g_cnt[t]     = 0.f;
}

// ---------------- point -> seed argmin + block-local segment sums ----------
__global__ void assign_kernel(const float* __restrict__ xyz,
                              const float* __restrict__ feat,
                              const int*   __restrict__ seed_idx) {
    __shared__ float s_sx[S_], s_sy[S_], s_sz[S_], s_s2[S_];
    __shared__ float s_acc[S_*8];
    int b     = blockIdx.x >> 4;
    int chunk = blockIdx.x & 15;
    int tid   = threadIdx.x;

    {
        int idx = seed_idx[tid];
        float a0 = xyz[(size_t)(b*N_ + idx)*3 + 0];
        float a1 = xyz[(size_t)(b*N_ + idx)*3 + 1];
        float a2 = xyz[(size_t)(b*N_ + idx)*3 + 2];
        s_sx[tid] = a0; s_sy[tid] = a1; s_sz[tid] = a2;
        s_s2[tid] = (a0*a0 + a1*a1) + a2*a2;
    }
    #pragma unroll
    for (int i = 0; i < 8; i++) s_acc[tid + i*256] = 0.f;
    __syncthreads();

    for (int p = 0; p < 8; p++) {
        int n = chunk*2048 + p*256 + tid;
        size_t off = (size_t)(b*N_ + n);
        float x0 = xyz[off*3+0], x1 = xyz[off*3+1], x2 = xyz[off*3+2];
        float x2s = (x0*x0 + x1*x1) + x2*x2;
        float best = INFINITY; int bi = 0;
        for (int s = 0; s < S_; s++) {
            float d = x0 * s_sx[s];
            d = fmaf(x1, s_sy[s], d);
            d = fmaf(x2, s_sz[s], d);
            float d2 = (x2s + s_s2[s]) - 2.0f*d;
            if (d2 < best) { best = d2; bi = s; }   // strict '<': first index wins
        }
        g_assign[off] = bi;
        float4 f = ((const float4*)feat)[off];
        float* a = &s_acc[bi*8];
        atomicAdd(a+0, x0);  atomicAdd(a+1, x1);  atomicAdd(a+2, x2);
        atomicAdd(a+3, f.x); atomicAdd(a+4, f.y); atomicAdd(a+5, f.z); atomicAdd(a+6, f.w);
        atomicAdd(a+7, 1.0f);
    }
    __syncthreads();

    int s  = tid;
    int bs = b*S_ + s;
    atomicAdd(&g_sumxyz [bs*3+0], s_acc[s*8+0]);
    atomicAdd(&g_sumxyz [bs*3+1], s_acc[s*8+1]);
    atomicAdd(&g_sumxyz [bs*3+2], s_acc[s*8+2]);
    atomicAdd(&g_sumfeat[bs*4+0], s_acc[s*8+3]);
    atomicAdd(&g_sumfeat[bs*4+1], s_acc[s*8+4]);
    atomicAdd(&g_sumfeat[bs*4+2], s_acc[s*8+5]);
    atomicAdd(&g_sumfeat[bs*4+3], s_acc[s*8+6]);
    atomicAdd(&g_cnt[bs],         s_acc[s*8+7]);
}

// ---------------- superpoint features -> token projection ----------
__global__ void tokens_kernel(const float* __restrict__ xyz,
                              const int*   __restrict__ seed_idx,
                              const float* __restrict__ pw,
                              const float* __restrict__ pb) {
    __shared__ float sp[7];
    int bs  = blockIdx.x;
    int b   = bs >> 8, s = bs & 255;
    int tid = threadIdx.x;
    if (tid == 0) {
        float cnt   = g_cnt[bs];
        float denom = fmaxf(cnt, 1.0f);
        bool  empty = (cnt == 0.0f);
        int   idx   = seed_idx[s];
        #pragma unroll
        for (int c = 0; c < 3; c++) {
            float seedc = xyz[(size_t)(b*N_ + idx)*3 + c];
            sp[c] = empty ? seedc : g_sumxyz[bs*3+c] / denom;
        }
        #pragma unroll
        for (int c = 0; c < 4; c++)
            sp[3+c] = empty ? 0.f : g_sumfeat[bs*4+c] / denom;
    }
    __syncthreads();
    float acc = 0.f;
    #pragma unroll
    for (int i = 0; i < 7; i++) acc = fmaf(sp[i], pw[tid*7 + i], acc);
    g_x[(size_t)bs*H_ + tid] = acc + pb[tid];
}

// ---------------- high-throughput SGEMM: C = epi(A(MxK) @ W(NxK)^T + bias) --
// 8x8 micro-tile per thread (split as 2x2 blocks of 4x4 at half-tile offsets),
// double-buffered SMEM (1 barrier per 16-k tile), register prefetch of LDG.
// EPI: 0 = none, 1 = gelu, 2 = +residual
template<int TM, int TN, int THREADS, int EPI>
__global__ void __launch_bounds__(THREADS)
sgemm_k(const float* __restrict__ A, const float* __restrict__ W,
        const float* __restrict__ bias, const float* __restrict__ res,
        float* __restrict__ C, int M, int N, int K) {
    constexpr int KT = 16;
    constexpr int PA = TM + 8;                       // 16B aligned + bank-spread
    constexpr int PB = (TN % 128 == 0) ? TN + 8 : TN + 4;
    constexpr int BX = TN / 8;                       // threads along N
    constexpr int NA = TM * 4 / THREADS;             // float4s of A per thread
    constexpr int NB = TN * 4 / THREADS;

    __shared__ float As[2][KT][PA];
    __shared__ float Ws[2][KT][PB];

    const int tid = threadIdx.x;
    const int tx  = tid % BX;
    const int ty  = tid / BX;                        // 0..15
    const int bm  = blockIdx.y * TM;
    const int bn  = blockIdx.x * TN;

    float4 pa[NA], pb[NB];
    float acc[2][2][4][4];
    #pragma unroll
    for (int a = 0; a < 2; a++)
        #pragma unroll
        for (int b = 0; b < 2; b++)
            #pragma unroll
            for (int i = 0; i < 4; i++)
                #pragma unroll
                for (int j = 0; j < 4; j++) acc[a][b][i][j] = 0.f;

    // prologue: load k-tile 0
    #pragma unroll
    for (int t = 0; t < NA; t++) {
        int id = tid + t*THREADS, r = id >> 2, c = id & 3;
        pa[t] = *(const float4*)(A + (size_t)(bm + r)*K + c*4);
    }
    #pragma unroll
    for (int t = 0; t < NB; t++) {
        int id = tid + t*THREADS, r = id >> 2, c = id & 3;
        pb[t] = *(const float4*)(W + (size_t)(bn + r)*K + c*4);
    }
    #pragma unroll
    for (int t = 0; t < NA; t++) {
        int id = tid + t*THREADS, r = id >> 2, c = id & 3;
        As[0][c*4+0][r] = pa[t].x; As[0][c*4+1][r] = pa[t].y;
        As[0][c*4+2][r] = pa[t].z; As[0][c*4+3][r] = pa[t].w;
    }
    #pragma unroll
    for (int t = 0; t < NB; t++) {
        int id = tid + t*THREADS, r = id >> 2, c = id & 3;
        Ws[0][c*4+0][r] = pb[t].x; Ws[0][c*4+1][r] = pb[t].y;
        Ws[0][c*4+2][r] = pb[t].z; Ws[0][c*4+3][r] = pb[t].w;
    }
    __syncthreads();

    const int nk = K / KT;
    for (int kt = 0; kt < nk; kt++) {
        int buf = kt & 1;
        if (kt + 1 < nk) {
            int k0 = (kt + 1) * KT;
            #pragma unroll
            for (int t = 0; t < NA; t++) {
                int id = tid + t*THREADS, r = id >> 2, c = id & 3;
                pa[t] = *(const float4*)(A + (size_t)(bm + r)*K + k0 + c*4);
            }
            #pragma unroll
            for (int t = 0; t < NB; t++) {
                int id = tid + t*THREADS, r = id >> 2, c = id & 3;
                pb[t] = *(const float4*)(W + (size_t)(bn + r)*K + k0 + c*4);
            }
        }
        #pragma unroll
        for (int k = 0; k < KT; k++) {
            float4 a0 = *(const float4*)&As[buf][k][ty*4];
            float4 a1 = *(const float4*)&As[buf][k][ty*4 + TM/2];
            float4 b0 = *(const float4*)&Ws[buf][k][tx*4];
            float4 b1 = *(const float4*)&Ws[buf][k][tx*4 + TN/2];
            float av[2][4] = {{a0.x, a0.y, a0.z, a0.w}, {a1.x, a1.y, a1.z, a1.w}};
            float bv[2][4] = {{b0.x, b0.y, b0.z, b0.w}, {b1.x, b1.y, b1.z, b1.w}};
            #pragma unroll
            for (int ih = 0; ih < 2; ih++)
                #pragma unroll
                for (int i = 0; i < 4; i++)
                    #pragma unroll
                    for (int jh = 0; jh < 2; jh++)
                        #pragma unroll
                        for (int j = 0; j < 4; j++)
                            acc[ih][jh][i][j] = fmaf(av[ih][i], bv[jh][j], acc[ih][jh][i][j]);
        }
        if (kt + 1 < nk) {
            int nb2 = buf ^ 1;
            #pragma unroll
            for (int t = 0; t < NA; t++) {
                int id = tid + t*THREADS, r = id >> 2, c = id & 3;
                As[nb2][c*4+0][r] = pa[t].x; As[nb2][c*4+1][r] = pa[t].y;
                As[nb2][c*4+2][r] = pa[t].z; As[nb2][c*4+3][r] = pa[t].w;
            }
            #pragma unroll
            for (int t = 0; t < NB; t++) {
                int id = tid + t*THREADS, r = id >> 2, c = id & 3;
                Ws[nb2][c*4+0][r] = pb[t].x; Ws[nb2][c*4+1][r] = pb[t].y;
                Ws[nb2][c*4+2][r] = pb[t].z; Ws[nb2][c*4+3][r] = pb[t].w;
            }
        }
        __syncthreads();
    }

    // epilogue
    #pragma unroll
    for (int ih = 0; ih < 2; ih++) {
        #pragma unroll
        for (int i = 0; i < 4; i++) {
            int row = bm + ih*(TM/2) + ty*4 + i;
            #pragma unroll
            for (int jh = 0; jh < 2; jh++) {
                int col = bn + jh*(TN/2) + tx*4;
                float4 bb = *(const float4*)(bias + col);
                float4 c;
                c.x = acc[ih][jh][i][0] + bb.x;
                c.y = acc[ih][jh][i][1] + bb.y;
                c.z = acc[ih][jh][i][2] + bb.z;
                c.w = acc[ih][jh][i][3] + bb.w;
                if (EPI == 1) {
                    c.x = gelu_exact(c.x); c.y = gelu_exact(c.y);
                    c.z = gelu_exact(c.z); c.w = gelu_exact(c.w);
                }
                if (EPI == 2) {
                    float4 rr = *(const float4*)(res + (size_t)row*N + col);
                    c.x += rr.x; c.y += rr.y; c.z += rr.z; c.w += rr.w;
                }
                *(float4*)(C + (size_t)row*N + col) = c;
            }
        }
    }
}

// ---------------- attention: one block per (b, head), thread = query row ----
__global__ void attention_kernel(const float* __restrict__ qkv,
                                 float* __restrict__ outp) {
    __shared__ float Ks[S_][DH_];
    int bh  = blockIdx.x;
    int b   = bh >> 3, h = bh & 7;
    int tid = threadIdx.x;
    const float* base = qkv + (size_t)b*S_*(3*H_);
    {
        const float4* kr = (const float4*)(base + (size_t)tid*(3*H_) + H_ + h*DH_);
        float4* dst = (float4*)&Ks[tid][0];
        #pragma unroll
        for (int i = 0; i < DH_/4; i++) dst[i] = kr[i];
    }
    float q[DH_];
    {
        const float4* qr = (const float4*)(base + (size_t)tid*(3*H_) + h*DH_);
        #pragma unroll
        for (int i = 0; i < DH_/4; i++) ((float4*)q)[i] = qr[i];
    }
    __syncthreads();

    const float scale = 0.17677669529663688110f;   // 1/sqrt(32)
    float m = -INFINITY, l = 0.f;
    float acc[DH_];
    #pragma unroll
    for (int d = 0; d < DH_; d++) acc[d] = 0.f;
    const float* vbase = base + 2*H_ + h*DH_;

    for (int j = 0; j < S_; j++) {
        float s = 0.f;
        #pragma unroll
        for (int d = 0; d < DH_; d++) s = fmaf(q[d], Ks[j][d], s);
        s *= scale;
        float mn = fmaxf(m, s);
        float c  = expf(m - mn);
        float p  = expf(s - mn);
        l = l*c + p;
        const float4* vr = (const float4*)(vbase + (size_t)j*(3*H_));
        #pragma unroll
        for (int i = 0; i < DH_/4; i++) {
            float4 vv = vr[i];
            acc[i*4+0] = fmaf(acc[i*4+0], c, p*vv.x);
            acc[i*4+1] = fmaf(acc[i*4+1], c, p*vv.y);
            acc[i*4+2] = fmaf(acc[i*4+2], c, p*vv.z);
            acc[i*4+3] = fmaf(acc[i*4+3], c, p*vv.w);
        }
        m = mn;
    }
    float inv = 1.0f / l;
    float* orow = outp + (size_t)(b*S_ + tid)*H_ + h*DH_;
    #pragma unroll
    for (int d = 0; d < DH_; d++) orow[d] = acc[d]*inv;
}

// ---------------- layernorm: one block (256 threads) per row ----------
__global__ void layernorm_kernel(const float* __restrict__ in,
                                 const float* __restrict__ gw,
                                 const float* __restrict__ gb,
                                 float* __restrict__ outp) {
    __shared__ float red[8];
    __shared__ float s_mean, s_var;
    int row = blockIdx.x, tid = threadIdx.x;
    float v = in[(size_t)row*H_ + tid];
    float s = v;
    #pragma unroll
    for (int o = 16; o > 0; o >>= 1) s += __shfl_xor_sync(0xffffffffu, s, o);
    if ((tid & 31) == 0) red[tid >> 5] = s;
    __syncthreads();
    if (tid == 0) {
        float t = 0.f;
        #pragma unroll
        for (int i = 0; i < 8; i++) t += red[i];
        s_mean = t * (1.0f/H_);
    }
    __syncthreads();
    float mean = s_mean;
    float d = v - mean;
    s = d*d;
    #pragma unroll
    for (int o = 16; o > 0; o >>= 1) s += __shfl_xor_sync(0xffffffffu, s, o);
    if ((tid & 31) == 0) red[tid >> 5] = s;
    __syncthreads();
    if (tid == 0) {
        float t = 0.f;
        #pragma unroll
        for (int i = 0; i < 8; i++) t += red[i];
        s_var = t * (1.0f/H_);
    }
    __syncthreads();
    outp[(size_t)row*H_ + tid] = d * rsqrtf(s_var + 1e-5f) * gw[tid] + gb[tid];
}

// ---------------- head2: logits (M x 13), one thread per output ----------
__global__ void head2_kernel(const float* __restrict__ X,
                             const float* __restrict__ W,
                             const float* __restrict__ bias) {
    int t = blockIdx.x * blockDim.x + threadIdx.x;
    if (t >= B_*S_*NC_) return;
    int row = t / NC_, c = t - row*NC_;
    const float4* x = (const float4*)(X + (size_t)row*H_);
    const float4* w = (const float4*)(W + (size_t)c*H_);
    float s0 = 0.f, s1 = 0.f, s2 = 0.f, s3 = 0.f;
    #pragma unroll 8
    for (int k = 0; k < H_/4; k++) {
        float4 xv = x[k], wv = w[k];
        s0 = fmaf(xv.x, wv.x, s0); s1 = fmaf(xv.y, wv.y, s1);
        s2 = fmaf(xv.z, wv.z, s2); s3 = fmaf(xv.w, wv.w, s3);
    }
    g_logits[t] = (s0+s1) + (s2+s3) + bias[c];
}

// ---------------- final gather to point logits ----------
__global__ void gather_kernel(float* __restrict__ out) {
    int t = blockIdx.x * blockDim.x + threadIdx.x;
    if (t >= B_*N_*NC_) return;
    int r = t / NC_;
    int c = t - r*NC_;
    int b = r >> 15;                // r / N_
    int a = g_assign[r];
    out[t] = g_logits[(b*S_ + a)*NC_ + c];
}

// ---------------- host launcher ----------
extern "C" void kernel_launch(void* const* d_in, const int* in_sizes, int n_in,
                              void* d_out, int out_size) {
    const float* xyz      = (const float*)d_in[0];
    const float* feat     = (const float*)d_in[1];
    const int*   seed_idx = (const int*)  d_in[2];
    const float* proj_w   = (const float*)d_in[3];
    const float* proj_b   = (const float*)d_in[4];
    const float* qkv_w    = (const float*)d_in[5];
    const float* qkv_b    = (const float*)d_in[6];
    const float* out_w    = (const float*)d_in[7];
    const float* out_b    = (const float*)d_in[8];
    const float* ln1_g    = (const float*)d_in[9];
    const float* ln1_b    = (const float*)d_in[10];
    const float* ln2_g    = (const float*)d_in[11];
    const float* ln2_b    = (const float*)d_in[12];
    const float* ff1_w    = (const float*)d_in[13];
    const float* ff1_b    = (const float*)d_in[14];
    const float* ff2_w    = (const float*)d_in[15];
    const float* ff2_b    = (const float*)d_in[16];
    const float* hln_g    = (const float*)d_in[17];
    const float* hln_b    = (const float*)d_in[18];
    const float* h1_w     = (const float*)d_in[19];
    const float* h1_b     = (const float*)d_in[20];
    const float* h2_w     = (const float*)d_in[21];
    const float* h2_b     = (const float*)d_in[22];
    float* out = (float*)d_out;

    float *p_x, *p_qkv, *p_attn, *p_tmp, *p_ff, *p_h1;
    cudaGetSymbolAddress((void**)&p_x,    g_x);
    cudaGetSymbolAddress((void**)&p_qkv,  g_qkv);
    cudaGetSymbolAddress((void**)&p_attn, g_attn);
    cudaGetSymbolAddress((void**)&p_tmp,  g_tmp);
    cudaGetSymbolAddress((void**)&p_ff,   g_ff);
    cudaGetSymbolAddress((void**)&p_h1,   g_h1);

    const int M = B_*S_;   // 4096

    zero_kernel<<<(B_*S_*4 + 255)/256, 256>>>();
    assign_kernel<<<B_*16, 256>>>(xyz, feat, seed_idx);
    tokens_kernel<<<B_*S_, 256>>>(xyz, seed_idx, proj_w, proj_b);

    for (int l = 0; l < 2; l++) {
        sgemm_k<128,128,256,0><<<dim3(3*H_/128, M/128), 256>>>(
            p_x, qkv_w + (size_t)l*3*H_*H_, qkv_b + l*3*H_, nullptr, p_qkv,
            M, 3*H_, H_);
        attention_kernel<<<B_*NH_, 256>>>(p_qkv, p_attn);
        sgemm_k<128,64,128,2><<<dim3(H_/64, M/128), 128>>>(
            p_attn, out_w + (size_t)l*H_*H_, out_b + l*H_, p_x, p_tmp,
            M, H_, H_);
        layernorm_kernel<<<M, 256>>>(p_tmp, ln1_g + l*H_, ln1_b + l*H_, p_x);
        sgemm_k<128,128,256,1><<<dim3(DFF_/128, M/128), 256>>>(
            p_x, ff1_w + (size_t)l*DFF_*H_, ff1_b + l*DFF_, nullptr, p_ff,
            M, DFF_, H_);
        sgemm_k<128,64,128,2><<<dim3(H_/64, M/128), 128>>>(
            p_ff, ff2_w + (size_t)l*H_*DFF_, ff2_b + l*H_, p_x, p_tmp,
            M, H_, DFF_);
        layernorm_kernel<<<M, 256>>>(p_tmp, ln2_g + l*H_, ln2_b + l*H_, p_x);
    }

    layernorm_kernel<<<M, 256>>>(p_x, hln_g, hln_b, p_tmp);
    sgemm_k<128,64,128,1><<<dim3(H_/64, M/128), 128>>>(
        p_tmp, h1_w, h1_b, nullptr, p_h1, M, H_, H_);
    head2_kernel<<<(M*NC_ + 255)/256, 256>>>(p_h1, h2_w, h2_b);
    gather_kernel<<<(B_*N_*NC_ + 255)/256, 256>>>(out);
}

// round 3
// speedup vs baseline: 1.1552x; 1.0374x over previous
#include <cuda_runtime.h>
#include <math.h>

#define B_   16
#define N_   32768
#define S_   256
#define H_   256
#define NH_  8
#define DH_  32
#define DFF_ 1024
#define NC_  13

// ---------------- scratch (device globals; no allocations allowed) ----------
__device__ float g_sumxyz[B_*S_*3];
__device__ float g_sumfeat[B_*S_*4];
__device__ float g_cnt[B_*S_];
__device__ int   g_assign[B_*N_];
__device__ float g_x[B_*S_*H_];
__device__ float g_qkv[B_*S_*3*H_];
__device__ float g_attn[B_*S_*H_];
__device__ float g_tmp[B_*S_*H_];
__device__ float g_ff[B_*S_*DFF_];
__device__ float g_h1[B_*S_*H_];
__device__ float g_logits[B_*S_*NC_];

// ---------------- utils ----------
__device__ __forceinline__ float gelu_exact(float x) {
    return 0.5f * x * (1.0f + erff(x * 0.70710678118654752440f));
}

// ---------------- zero the segment accumulators ----------
__global__ void zero_kernel() {
    int t = blockIdx.x * blockDim.x + threadIdx.x;
    if (t < B_*S_*3) g_sumxyz[t]  = 0.f;
    if (t < B_*S_*4) g_sumfeat[t] = 0.f;
    if (t < B_*S_)   g_cnt[t]     = 0.f;
}

// ---------------- point -> seed argmin + block-local segment sums ----------
__global__ void assign_kernel(const float* __restrict__ xyz,
                              const float* __restrict__ feat,
                              const int*   __restrict__ seed_idx) {
    __shared__ float s_sx[S_], s_sy[S_], s_sz[S_], s_s2[S_];
    __shared__ float s_acc[S_*8];
    int b     = blockIdx.x >> 4;
    int chunk = blockIdx.x & 15;
    int tid   = threadIdx.x;

    {
        int idx = seed_idx[tid];
        float a0 = xyz[(size_t)(b*N_ + idx)*3 + 0];
        float a1 = xyz[(size_t)(b*N_ + idx)*3 + 1];
        float a2 = xyz[(size_t)(b*N_ + idx)*3 + 2];
        s_sx[tid] = a0; s_sy[tid] = a1; s_sz[tid] = a2;
        s_s2[tid] = (a0*a0 + a1*a1) + a2*a2;
    }
    #pragma unroll
    for (int i = 0; i < 8; i++) s_acc[tid + i*256] = 0.f;
    __syncthreads();

    for (int p = 0; p < 8; p++) {
        int n = chunk*2048 + p*256 + tid;
        size_t off = (size_t)(b*N_ + n);
        float x0 = xyz[off*3+0], x1 = xyz[off*3+1], x2 = xyz[off*3+2];
        float x2s = (x0*x0 + x1*x1) + x2*x2;
        float best = INFINITY; int bi = 0;
        for (int s = 0; s < S_; s++) {
            float d = x0 * s_sx[s];
            d = fmaf(x1, s_sy[s], d);
            d = fmaf(x2, s_sz[s], d);
            float d2 = (x2s + s_s2[s]) - 2.0f*d;
            if (d2 < best) { best = d2; bi = s; }   // strict '<': first index wins
        }
        g_assign[off] = bi;
        float4 f = ((const float4*)feat)[off];
        float* a = &s_acc[bi*8];
        atomicAdd(a+0, x0);  atomicAdd(a+1, x1);  atomicAdd(a+2, x2);
        atomicAdd(a+3, f.x); atomicAdd(a+4, f.y); atomicAdd(a+5, f.z); atomicAdd(a+6, f.w);
        atomicAdd(a+7, 1.0f);
    }
    __syncthreads();

    int s  = tid;
    int bs = b*S_ + s;
    atomicAdd(&g_sumxyz [bs*3+0], s_acc[s*8+0]);
    atomicAdd(&g_sumxyz [bs*3+1], s_acc[s*8+1]);
    atomicAdd(&g_sumxyz [bs*3+2], s_acc[s*8+2]);
    atomicAdd(&g_sumfeat[bs*4+0], s_acc[s*8+3]);
    atomicAdd(&g_sumfeat[bs*4+1], s_acc[s*8+4]);
    atomicAdd(&g_sumfeat[bs*4+2], s_acc[s*8+5]);
    atomicAdd(&g_sumfeat[bs*4+3], s_acc[s*8+6]);
    atomicAdd(&g_cnt[bs],         s_acc[s*8+7]);
}

// ---------------- superpoint features -> token projection ----------
__global__ void tokens_kernel(const float* __restrict__ xyz,
                              const int*   __restrict__ seed_idx,
                              const float* __restrict__ pw,
                              const float* __restrict__ pb) {
    __shared__ float sp[7];
    int bs  = blockIdx.x;
    int b   = bs >> 8, s = bs & 255;
    int tid = threadIdx.x;
    if (tid == 0) {
        float cnt   = g_cnt[bs];
        float denom = fmaxf(cnt, 1.0f);
        bool  empty = (cnt == 0.0f);
        int   idx   = seed_idx[s];
        #pragma unroll
        for (int c = 0; c < 3; c++) {
            float seedc = xyz[(size_t)(b*N_ + idx)*3 + c];
            sp[c] = empty ? seedc : g_sumxyz[bs*3+c] / denom;
        }
        #pragma unroll
        for (int c = 0; c < 4; c++)
            sp[3+c] = empty ? 0.f : g_sumfeat[bs*4+c] / denom;
    }
    __syncthreads();
    float acc = 0.f;
    #pragma unroll
    for (int i = 0; i < 7; i++) acc = fmaf(sp[i], pw[tid*7 + i], acc);
    g_x[(size_t)bs*H_ + tid] = acc + pb[tid];
}

// ---------------- high-throughput SGEMM: C = epi(A(MxK) @ W(NxK)^T + bias) --
// 8x8 micro-tile per thread (2x2 blocks of 4x4 at half-tile offsets),
// double-buffered SMEM, register prefetch, occupancy pinned via launch_bounds.
// EPI: 0 = none, 1 = gelu, 2 = +residual
template<int TM, int TN, int KT, int THREADS, int MINCTA, int EPI>
__global__ void __launch_bounds__(THREADS, MINCTA)
sgemm_k(const float* __restrict__ A, const float* __restrict__ W,
        const float* __restrict__ bias, const float* __restrict__ res,
        float* __restrict__ C, int M, int N, int K) {
    constexpr int PA = TM + 8;
    constexpr int PB = (TN % 128 == 0) ? TN + 8 : TN + 4;
    constexpr int BX = TN / 8;                       // threads along N
    constexpr int K4 = KT / 4;                       // float4s per k-row
    constexpr int NA = TM * K4 / THREADS;            // A float4s per thread
    constexpr int NB = TN * K4 / THREADS;

    __shared__ float As[2][KT][PA];
    __shared__ float Ws[2][KT][PB];

    const int tid = threadIdx.x;
    const int tx  = tid % BX;
    const int ty  = tid / BX;                        // 0..15
    const int bm  = blockIdx.y * TM;
    const int bn  = blockIdx.x * TN;

    float4 pa[NA], pb[NB];
    float acc[2][2][4][4];
    #pragma unroll
    for (int a = 0; a < 2; a++)
        #pragma unroll
        for (int b = 0; b < 2; b++)
            #pragma unroll
            for (int i = 0; i < 4; i++)
                #pragma unroll
                for (int j = 0; j < 4; j++) acc[a][b][i][j] = 0.f;

    // prologue: load k-tile 0
    #pragma unroll
    for (int t = 0; t < NA; t++) {
        int id = tid + t*THREADS, r = id / K4, c = id % K4;
        pa[t] = *(const float4*)(A + (size_t)(bm + r)*K + c*4);
    }
    #pragma unroll
    for (int t = 0; t < NB; t++) {
        int id = tid + t*THREADS, r = id / K4, c = id % K4;
        pb[t] = *(const float4*)(W + (size_t)(bn + r)*K + c*4);
    }
    #pragma unroll
    for (int t = 0; t < NA; t++) {
        int id = tid + t*THREADS, r = id / K4, c = id % K4;
        As[0][c*4+0][r] = pa[t].x; As[0][c*4+1][r] = pa[t].y;
        As[0][c*4+2][r] = pa[t].z; As[0][c*4+3][r] = pa[t].w;
    }
    #pragma unroll
    for (int t = 0; t < NB; t++) {
        int id = tid + t*THREADS, r = id / K4, c = id % K4;
        Ws[0][c*4+0][r] = pb[t].x; Ws[0][c*4+1][r] = pb[t].y;
        Ws[0][c*4+2][r] = pb[t].z; Ws[0][c*4+3][r] = pb[t].w;
    }
    __syncthreads();

    const int nk = K / KT;
    for (int kt = 0; kt < nk; kt++) {
        int buf = kt & 1;
        if (kt + 1 < nk) {
            int k0 = (kt + 1) * KT;
            #pragma unroll
            for (int t = 0; t < NA; t++) {
                int id = tid + t*THREADS, r = id / K4, c = id % K4;
                pa[t] = *(const float4*)(A + (size_t)(bm + r)*K + k0 + c*4);
            }
            #pragma unroll
            for (int t = 0; t < NB; t++) {
                int id = tid + t*THREADS, r = id / K4, c = id % K4;
                pb[t] = *(const float4*)(W + (size_t)(bn + r)*K + k0 + c*4);
            }
        }
        #pragma unroll
        for (int k = 0; k < KT; k++) {
            float4 a0 = *(const float4*)&As[buf][k][ty*4];
            float4 a1 = *(const float4*)&As[buf][k][ty*4 + TM/2];
            float4 b0 = *(const float4*)&Ws[buf][k][tx*4];
            float4 b1 = *(const float4*)&Ws[buf][k][tx*4 + TN/2];
            float av[2][4] = {{a0.x, a0.y, a0.z, a0.w}, {a1.x, a1.y, a1.z, a1.w}};
            float bv[2][4] = {{b0.x, b0.y, b0.z, b0.w}, {b1.x, b1.y, b1.z, b1.w}};
            #pragma unroll
            for (int ih = 0; ih < 2; ih++)
                #pragma unroll
                for (int i = 0; i < 4; i++)
                    #pragma unroll
                    for (int jh = 0; jh < 2; jh++)
                        #pragma unroll
                        for (int j = 0; j < 4; j++)
                            acc[ih][jh][i][j] = fmaf(av[ih][i], bv[jh][j], acc[ih][jh][i][j]);
        }
        if (kt + 1 < nk) {
            int nb2 = buf ^ 1;
            #pragma unroll
            for (int t = 0; t < NA; t++) {
                int id = tid + t*THREADS, r = id / K4, c = id % K4;
                As[nb2][c*4+0][r] = pa[t].x; As[nb2][c*4+1][r] = pa[t].y;
                As[nb2][c*4+2][r] = pa[t].z; As[nb2][c*4+3][r] = pa[t].w;
            }
            #pragma unroll
            for (int t = 0; t < NB; t++) {
                int id = tid + t*THREADS, r = id / K4, c = id % K4;
                Ws[nb2][c*4+0][r] = pb[t].x; Ws[nb2][c*4+1][r] = pb[t].y;
                Ws[nb2][c*4+2][r] = pb[t].z; Ws[nb2][c*4+3][r] = pb[t].w;
            }
        }
        __syncthreads();
    }

    // epilogue
    #pragma unroll
    for (int ih = 0; ih < 2; ih++) {
        #pragma unroll
        for (int i = 0; i < 4; i++) {
            int row = bm + ih*(TM/2) + ty*4 + i;
            #pragma unroll
            for (int jh = 0; jh < 2; jh++) {
                int col = bn + jh*(TN/2) + tx*4;
                float4 bb = *(const float4*)(bias + col);
                float4 c;
                c.x = acc[ih][jh][i][0] + bb.x;
                c.y = acc[ih][jh][i][1] + bb.y;
                c.z = acc[ih][jh][i][2] + bb.z;
                c.w = acc[ih][jh][i][3] + bb.w;
                if (EPI == 1) {
                    c.x = gelu_exact(c.x); c.y = gelu_exact(c.y);
                    c.z = gelu_exact(c.z); c.w = gelu_exact(c.w);
                }
                if (EPI == 2) {
                    float4 rr = *(const float4*)(res + (size_t)row*N + col);
                    c.x += rr.x; c.y += rr.y; c.z += rr.z; c.w += rr.w;
                }
                *(float4*)(C + (size_t)row*N + col) = c;
            }
        }
    }
}

// ---------------- attention: one block per (b, head), thread = query row ----
__global__ void attention_kernel(const float* __restrict__ qkv,
                                 float* __restrict__ outp) {
    __shared__ float Ks[S_][DH_];
    int bh  = blockIdx.x;
    int b   = bh >> 3, h = bh & 7;
    int tid = threadIdx.x;
    const float* base = qkv + (size_t)b*S_*(3*H_);
    {
        const float4* kr = (const float4*)(base + (size_t)tid*(3*H_) + H_ + h*DH_);
        float4* dst = (float4*)&Ks[tid][0];
        #pragma unroll
        for (int i = 0; i < DH_/4; i++) dst[i] = kr[i];
    }
    float q[DH_];
    {
        const float4* qr = (const float4*)(base + (size_t)tid*(3*H_) + h*DH_);
        #pragma unroll
        for (int i = 0; i < DH_/4; i++) ((float4*)q)[i] = qr[i];
    }
    __syncthreads();

    const float scale = 0.17677669529663688110f;   // 1/sqrt(32)
    float m = -INFINITY, l = 0.f;
    float acc[DH_];
    #pragma unroll
    for (int d = 0; d < DH_; d++) acc[d] = 0.f;
    const float* vbase = base + 2*H_ + h*DH_;

    for (int j = 0; j < S_; j++) {
        float s = 0.f;
        #pragma unroll
        for (int d = 0; d < DH_; d++) s = fmaf(q[d], Ks[j][d], s);
        s *= scale;
        float mn = fmaxf(m, s);
        float c  = __expf(m - mn);
        float p  = __expf(s - mn);
        l = l*c + p;
        const float4* vr = (const float4*)(vbase + (size_t)j*(3*H_));
        #pragma unroll
        for (int i = 0; i < DH_/4; i++) {
            float4 vv = vr[i];
            acc[i*4+0] = fmaf(acc[i*4+0], c, p*vv.x);
            acc[i*4+1] = fmaf(acc[i*4+1], c, p*vv.y);
            acc[i*4+2] = fmaf(acc[i*4+2], c, p*vv.z);
            acc[i*4+3] = fmaf(acc[i*4+3], c, p*vv.w);
        }
        m = mn;
    }
    float inv = 1.0f / l;
    float* orow = outp + (size_t)(b*S_ + tid)*H_ + h*DH_;
    #pragma unroll
    for (int d = 0; d < DH_; d++) orow[d] = acc[d]*inv;
}

// ---------------- layernorm: one block (256 threads) per row ----------
__global__ void layernorm_kernel(const float* __restrict__ in,
                                 const float* __restrict__ gw,
                                 const float* __restrict__ gb,
                                 float* __restrict__ outp) {
    __shared__ float red[8];
    __shared__ float s_mean, s_var;
    int row = blockIdx.x, tid = threadIdx.x;
    float v = in[(size_t)row*H_ + tid];
    float s = v;
    #pragma unroll
    for (int o = 16; o > 0; o >>= 1) s += __shfl_xor_sync(0xffffffffu, s, o);
    if ((tid & 31) == 0) red[tid >> 5] = s;
    __syncthreads();
    if (tid == 0) {
        float t = 0.f;
        #pragma unroll
        for (int i = 0; i < 8; i++) t += red[i];
        s_mean = t * (1.0f/H_);
    }
    __syncthreads();
    float mean = s_mean;
    float d = v - mean;
    s = d*d;
    #pragma unroll
    for (int o = 16; o > 0; o >>= 1) s += __shfl_xor_sync(0xffffffffu, s, o);
    if ((tid & 31) == 0) red[tid >> 5] = s;
    __syncthreads();
    if (tid == 0) {
        float t = 0.f;
        #pragma unroll
        for (int i = 0; i < 8; i++) t += red[i];
        s_var = t * (1.0f/H_);
    }
    __syncthreads();
    outp[(size_t)row*H_ + tid] = d * rsqrtf(s_var + 1e-5f) * gw[tid] + gb[tid];
}

// ---------------- head2: logits (M x 13), one thread per output ----------
__global__ void head2_kernel(const float* __restrict__ X,
                             const float* __restrict__ W,
                             const float* __restrict__ bias) {
    int t = blockIdx.x * blockDim.x + threadIdx.x;
    if (t >= B_*S_*NC_) return;
    int row = t / NC_, c = t - row*NC_;
    const float4* x = (const float4*)(X + (size_t)row*H_);
    const float4* w = (const float4*)(W + (size_t)c*H_);
    float s0 = 0.f, s1 = 0.f, s2 = 0.f, s3 = 0.f;
    #pragma unroll 8
    for (int k = 0; k < H_/4; k++) {
        float4 xv = x[k], wv = w[k];
        s0 = fmaf(xv.x, wv.x, s0); s1 = fmaf(xv.y, wv.y, s1);
        s2 = fmaf(xv.z, wv.z, s2); s3 = fmaf(xv.w, wv.w, s3);
    }
    g_logits[t] = (s0+s1) + (s2+s3) + bias[c];
}

// ---------------- final gather to point logits ----------
__global__ void gather_kernel(float* __restrict__ out) {
    int t = blockIdx.x * blockDim.x + threadIdx.x;
    if (t >= B_*N_*NC_) return;
    int r = t / NC_;
    int c = t - r*NC_;
    int b = r >> 15;                // r / N_
    int a = g_assign[r];
    out[t] = g_logits[(b*S_ + a)*NC_ + c];
}

// ---------------- host launcher ----------
extern "C" void kernel_launch(void* const* d_in, const int* in_sizes, int n_in,
                              void* d_out, int out_size) {
    const float* xyz      = (const float*)d_in[0];
    const float* feat     = (const float*)d_in[1];
    const int*   seed_idx = (const int*)  d_in[2];
    const float* proj_w   = (const float*)d_in[3];
    const float* proj_b   = (const float*)d_in[4];
    const float* qkv_w    = (const float*)d_in[5];
    const float* qkv_b    = (const float*)d_in[6];
    const float* out_w    = (const float*)d_in[7];
    const float* out_b    = (const float*)d_in[8];
    const float* ln1_g    = (const float*)d_in[9];
    const float* ln1_b    = (const float*)d_in[10];
    const float* ln2_g    = (const float*)d_in[11];
    const float* ln2_b    = (const float*)d_in[12];
    const float* ff1_w    = (const float*)d_in[13];
    const float* ff1_b    = (const float*)d_in[14];
    const float* ff2_w    = (const float*)d_in[15];
    const float* ff2_b    = (const float*)d_in[16];
    const float* hln_g    = (const float*)d_in[17];
    const float* hln_b    = (const float*)d_in[18];
    const float* h1_w     = (const float*)d_in[19];
    const float* h1_b     = (const float*)d_in[20];
    const float* h2_w     = (const float*)d_in[21];
    const float* h2_b     = (const float*)d_in[22];
    float* out = (float*)d_out;

    float *p_x, *p_qkv, *p_attn, *p_tmp, *p_ff, *p_h1;
    cudaGetSymbolAddress((void**)&p_x,    g_x);
    cudaGetSymbolAddress((void**)&p_qkv,  g_qkv);
    cudaGetSymbolAddress((void**)&p_attn, g_attn);
    cudaGetSymbolAddress((void**)&p_tmp,  g_tmp);
    cudaGetSymbolAddress((void**)&p_ff,   g_ff);
    cudaGetSymbolAddress((void**)&p_h1,   g_h1);

    const int M = B_*S_;   // 4096

    zero_kernel<<<(B_*S_*4 + 255)/256, 256>>>();
    assign_kernel<<<B_*16, 256>>>(xyz, feat, seed_idx);
    tokens_kernel<<<B_*S_, 256>>>(xyz, seed_idx, proj_w, proj_b);

    for (int l = 0; l < 2; l++) {
        sgemm_k<128,128,8,256,2,0><<<dim3(3*H_/128, M/128), 256>>>(
            p_x, qkv_w + (size_t)l*3*H_*H_, qkv_b + l*3*H_, nullptr, p_qkv,
            M, 3*H_, H_);
        attention_kernel<<<B_*NH_, 256>>>(p_qkv, p_attn);
        sgemm_k<128,64,16,128,3,2><<<dim3(H_/64, M/128), 128>>>(
            p_attn, out_w + (size_t)l*H_*H_, out_b + l*H_, p_x, p_tmp,
            M, H_, H_);
        layernorm_kernel<<<M, 256>>>(p_tmp, ln1_g + l*H_, ln1_b + l*H_, p_x);
        sgemm_k<128,128,8,256,2,1><<<dim3(DFF_/128, M/128), 256>>>(
            p_x, ff1_w + (size_t)l*DFF_*H_, ff1_b + l*DFF_, nullptr, p_ff,
            M, DFF_, H_);
        sgemm_k<128,64,16,128,3,2><<<dim3(H_/64, M/128), 128>>>(
            p_ff, ff2_w + (size_t)l*H_*DFF_, ff2_b + l*H_, p_x, p_tmp,
            M, H_, DFF_);
        layernorm_kernel<<<M, 256>>>(p_tmp, ln2_g + l*H_, ln2_b + l*H_, p_x);
    }

    layernorm_kernel<<<M, 256>>>(p_x, hln_g, hln_b, p_tmp);
    sgemm_k<128,64,16,128,3,1><<<dim3(H_/64, M/128), 128>>>(
        p_tmp, h1_w, h1_b, nullptr, p_h1, M, H_, H_);
    head2_kernel<<<(M*NC_ + 255)/256, 256>>>(p_h1, h2_w, h2_b);
    gather_kernel<<<(B_*N_*NC_ + 255)/256, 256>>>(out);
}

// round 4
// speedup vs baseline: 1.2351x; 1.0692x over previous
#include <cuda_runtime.h>
#include <math.h>
#include <stdint.h>

#define B_   16
#define N_   32768
#define S_   256
#define H_   256
#define NH_  8
#define DH_  32
#define DFF_ 1024
#define NC_  13

// ---------------- scratch (device globals; no allocations allowed) ----------
__device__ float g_sumxyz[B_*S_*3];
__device__ float g_sumfeat[B_*S_*4];
__device__ float g_cnt[B_*S_];
__device__ int   g_assign[B_*N_];
__device__ float g_x[B_*S_*H_];
__device__ float g_qkv[B_*S_*3*H_];
__device__ float g_attn[B_*S_*H_];
__device__ float g_tmp[B_*S_*H_];
__device__ float g_ff[B_*S_*DFF_];
__device__ float g_h1[B_*S_*H_];
__device__ float g_logits[B_*S_*NC_];

// ---------------- utils ----------
__device__ __forceinline__ float gelu_exact(float x) {
    return 0.5f * x * (1.0f + erff(x * 0.70710678118654752440f));
}

__device__ __forceinline__ uint32_t f2tf32(float x) {
    uint32_t r;
    asm("cvt.rna.tf32.f32 %0, %1;" : "=r"(r) : "f"(x));
    return r;
}

__device__ __forceinline__ void mma_tf32(float* d, const uint32_t* a,
                                         uint32_t b0, uint32_t b1) {
    asm volatile(
        "mma.sync.aligned.m16n8k8.row.col.f32.tf32.tf32.f32 "
        "{%0,%1,%2,%3},{%4,%5,%6,%7},{%8,%9},{%0,%1,%2,%3};"
        : "+f"(d[0]), "+f"(d[1]), "+f"(d[2]), "+f"(d[3])
        : "r"(a[0]), "r"(a[1]), "r"(a[2]), "r"(a[3]), "r"(b0), "r"(b1));
}

// ---------------- zero the segment accumulators ----------
__global__ void zero_kernel() {
    int t = blockIdx.x * blockDim.x + threadIdx.x;
    if (t < B_*S_*3) g_sumxyz[t]  = 0.f;
    if (t < B_*S_*4) g_sumfeat[t] = 0.f;
    if (t < B_*S_)   g_cnt[t]     = 0.f;
}

// ---------------- point -> seed argmin + block-local segment sums ----------
__global__ void assign_kernel(const float* __restrict__ xyz,
                              const float* __restrict__ feat,
                              const int*   __restrict__ seed_idx) {
    __shared__ float s_sx[S_], s_sy[S_], s_sz[S_], s_s2[S_];
    __shared__ float s_acc[S_*8];
    int b     = blockIdx.x >> 4;
    int chunk = blockIdx.x & 15;
    int tid   = threadIdx.x;

    {
        int idx = seed_idx[tid];
        float a0 = xyz[(size_t)(b*N_ + idx)*3 + 0];
        float a1 = xyz[(size_t)(b*N_ + idx)*3 + 1];
        float a2 = xyz[(size_t)(b*N_ + idx)*3 + 2];
        s_sx[tid] = a0; s_sy[tid] = a1; s_sz[tid] = a2;
        s_s2[tid] = (a0*a0 + a1*a1) + a2*a2;
    }
    #pragma unroll
    for (int i = 0; i < 8; i++) s_acc[tid + i*256] = 0.f;
    __syncthreads();

    for (int p = 0; p < 8; p++) {
        int n = chunk*2048 + p*256 + tid;
        size_t off = (size_t)(b*N_ + n);
        float x0 = xyz[off*3+0], x1 = xyz[off*3+1], x2 = xyz[off*3+2];
        float x2s = (x0*x0 + x1*x1) + x2*x2;
        float best = INFINITY; int bi = 0;
        for (int s = 0; s < S_; s++) {
            float d = x0 * s_sx[s];
            d = fmaf(x1, s_sy[s], d);
            d = fmaf(x2, s_sz[s], d);
            float d2 = (x2s + s_s2[s]) - 2.0f*d;
            if (d2 < best) { best = d2; bi = s; }   // strict '<': first index wins
        }
        g_assign[off] = bi;
        float4 f = ((const float4*)feat)[off];
        float* a = &s_acc[bi*8];
        atomicAdd(a+0, x0);  atomicAdd(a+1, x1);  atomicAdd(a+2, x2);
        atomicAdd(a+3, f.x); atomicAdd(a+4, f.y); atomicAdd(a+5, f.z); atomicAdd(a+6, f.w);
        atomicAdd(a+7, 1.0f);
    }
    __syncthreads();

    int s  = tid;
    int bs = b*S_ + s;
    atomicAdd(&g_sumxyz [bs*3+0], s_acc[s*8+0]);
    atomicAdd(&g_sumxyz [bs*3+1], s_acc[s*8+1]);
    atomicAdd(&g_sumxyz [bs*3+2], s_acc[s*8+2]);
    atomicAdd(&g_sumfeat[bs*4+0], s_acc[s*8+3]);
    atomicAdd(&g_sumfeat[bs*4+1], s_acc[s*8+4]);
    atomicAdd(&g_sumfeat[bs*4+2], s_acc[s*8+5]);
    atomicAdd(&g_sumfeat[bs*4+3], s_acc[s*8+6]);
    atomicAdd(&g_cnt[bs],         s_acc[s*8+7]);
}

// ---------------- superpoint features -> token projection ----------
__global__ void tokens_kernel(const float* __restrict__ xyz,
                              const int*   __restrict__ seed_idx,
                              const float* __restrict__ pw,
                              const float* __restrict__ pb) {
    __shared__ float sp[7];
    int bs  = blockIdx.x;
    int b   = bs >> 8, s = bs & 255;
    int tid = threadIdx.x;
    if (tid == 0) {
        float cnt   = g_cnt[bs];
        float denom = fmaxf(cnt, 1.0f);
        bool  empty = (cnt == 0.0f);
        int   idx   = seed_idx[s];
        #pragma unroll
        for (int c = 0; c < 3; c++) {
            float seedc = xyz[(size_t)(b*N_ + idx)*3 + c];
            sp[c] = empty ? seedc : g_sumxyz[bs*3+c] / denom;
        }
        #pragma unroll
        for (int c = 0; c < 4; c++)
            sp[3+c] = empty ? 0.f : g_sumfeat[bs*4+c] / denom;
    }
    __syncthreads();
    float acc = 0.f;
    #pragma unroll
    for (int i = 0; i < 7; i++) acc = fmaf(sp[i], pw[tid*7 + i], acc);
    g_x[(size_t)bs*H_ + tid] = acc + pb[tid];
}

// ---------------- tensor-core GEMM (3xTF32): C = epi(A @ W^T + bias) --------
// A: MxK row-major, W: NxK row-major. hi/lo split recovers fp32 precision:
//   acc += a_lo*b_hi + a_hi*b_lo + a_hi*b_hi   (lo*lo term ~2^-22, dropped)
// KT=8, double-buffered SMEM, +8 pad => conflict-free fragment LDS.
// EPI: 0 = none, 1 = gelu, 2 = +residual
template<int TM, int TN, int WM, int WN, int THREADS, int MINCTA, int EPI>
__global__ void __launch_bounds__(THREADS, MINCTA)
sgemm_tc(const float* __restrict__ A, const float* __restrict__ W,
         const float* __restrict__ bias, const float* __restrict__ res,
         float* __restrict__ C, int M, int N, int K) {
    constexpr int KT = 8;
    constexpr int PA = TM + 8;
    constexpr int PB = TN + 8;
    constexpr int WCOLS = TN / WN;
    constexpr int MT = WM / 16;
    constexpr int NT = WN / 8;

    __shared__ uint32_t As_hi[2][KT][PA];
    __shared__ uint32_t As_lo[2][KT][PA];
    __shared__ uint32_t Ws_hi[2][KT][PB];
    __shared__ uint32_t Ws_lo[2][KT][PB];

    const int tid  = threadIdx.x;
    const int lane = tid & 31;
    const int wid  = tid >> 5;
    const int wrow = wid / WCOLS;
    const int wcol = wid % WCOLS;
    const int gr   = lane >> 2;          // 0..7
    const int ct   = lane & 3;           // 0..3
    const int bm   = blockIdx.y * TM;
    const int bn   = blockIdx.x * TN;

    // loader coords: thread -> (row, float4-within-KT)
    const int lr = tid >> 1;             // 0..TM-1 (TM*2 == THREADS)
    const int lc = (tid & 1) * 4;        // k base 0 or 4

    float acc[MT][NT][4];
    #pragma unroll
    for (int mt = 0; mt < MT; mt++)
        #pragma unroll
        for (int nt = 0; nt < NT; nt++)
            #pragma unroll
            for (int j = 0; j < 4; j++) acc[mt][nt][j] = 0.f;

    const float* Ap = A + (size_t)(bm + lr)*K + lc;
    const float* Wp = W + (size_t)(bn + lr)*K + lc;

    float4 av = *(const float4*)(Ap);
    float4 wv = *(const float4*)(Wp);

    // convert + store helper (macro-free, inlined)
    auto stage = [&](int buf, float4 a, float4 w) {
        float af[4] = {a.x, a.y, a.z, a.w};
        float wf[4] = {w.x, w.y, w.z, w.w};
        #pragma unroll
        for (int j = 0; j < 4; j++) {
            uint32_t hi = f2tf32(af[j]);
            float lof = af[j] - __uint_as_float(hi);
            As_hi[buf][lc + j][lr] = hi;
            As_lo[buf][lc + j][lr] = f2tf32(lof);
        }
        #pragma unroll
        for (int j = 0; j < 4; j++) {
            uint32_t hi = f2tf32(wf[j]);
            float lof = wf[j] - __uint_as_float(hi);
            Ws_hi[buf][lc + j][lr] = hi;
            Ws_lo[buf][lc + j][lr] = f2tf32(lof);
        }
    };

    stage(0, av, wv);
    __syncthreads();

    const int nk = K / KT;
    for (int kt = 0; kt < nk; kt++) {
        const int buf = kt & 1;
        if (kt + 1 < nk) {
            av = *(const float4*)(Ap + (kt + 1)*KT);
            wv = *(const float4*)(Wp + (kt + 1)*KT);
        }

        // load A fragments (hi+lo) for all m-tiles
        uint32_t ah[MT][4], al[MT][4];
        #pragma unroll
        for (int mt = 0; mt < MT; mt++) {
            int m = wrow*WM + mt*16 + gr;
            ah[mt][0] = As_hi[buf][ct  ][m];
            ah[mt][1] = As_hi[buf][ct  ][m + 8];
            ah[mt][2] = As_hi[buf][ct+4][m];
            ah[mt][3] = As_hi[buf][ct+4][m + 8];
            al[mt][0] = As_lo[buf][ct  ][m];
            al[mt][1] = As_lo[buf][ct  ][m + 8];
            al[mt][2] = As_lo[buf][ct+4][m];
            al[mt][3] = As_lo[buf][ct+4][m + 8];
        }
        #pragma unroll
        for (int nt = 0; nt < NT; nt++) {
            int n = wcol*WN + nt*8 + gr;
            uint32_t bh0 = Ws_hi[buf][ct  ][n];
            uint32_t bh1 = Ws_hi[buf][ct+4][n];
            uint32_t bl0 = Ws_lo[buf][ct  ][n];
            uint32_t bl1 = Ws_lo[buf][ct+4][n];
            #pragma unroll
            for (int mt = 0; mt < MT; mt++) {
                mma_tf32(acc[mt][nt], al[mt], bh0, bh1);   // lo*hi
                mma_tf32(acc[mt][nt], ah[mt], bl0, bl1);   // hi*lo
                mma_tf32(acc[mt][nt], ah[mt], bh0, bh1);   // hi*hi
            }
        }

        if (kt + 1 < nk) stage(buf ^ 1, av, wv);
        __syncthreads();
    }

    // epilogue: C-frag layout m16n8: (gr, ct*2), (gr, ct*2+1), (+8 rows)
    #pragma unroll
    for (int mt = 0; mt < MT; mt++) {
        int row = bm + wrow*WM + mt*16 + gr;
        #pragma unroll
        for (int nt = 0; nt < NT; nt++) {
            int col = bn + wcol*WN + nt*8 + ct*2;
            float b0 = bias[col], b1 = bias[col + 1];
            float c0 = acc[mt][nt][0] + b0;
            float c1 = acc[mt][nt][1] + b1;
            float c2 = acc[mt][nt][2] + b0;
            float c3 = acc[mt][nt][3] + b1;
            if (EPI == 1) {
                c0 = gelu_exact(c0); c1 = gelu_exact(c1);
                c2 = gelu_exact(c2); c3 = gelu_exact(c3);
            }
            if (EPI == 2) {
                float2 r0 = *(const float2*)(res + (size_t)row*N + col);
                float2 r1 = *(const float2*)(res + (size_t)(row + 8)*N + col);
                c0 += r0.x; c1 += r0.y; c2 += r1.x; c3 += r1.y;
            }
            *(float2*)(C + (size_t)row*N + col)       = make_float2(c0, c1);
            *(float2*)(C + (size_t)(row + 8)*N + col) = make_float2(c2, c3);
        }
    }
}

// ---------------- attention: one block per (b, head), thread = query row ----
__global__ void attention_kernel(const float* __restrict__ qkv,
                                 float* __restrict__ outp) {
    __shared__ float Ks[S_][DH_];
    int bh  = blockIdx.x;
    int b   = bh >> 3, h = bh & 7;
    int tid = threadIdx.x;
    const float* base = qkv + (size_t)b*S_*(3*H_);
    {
        const float4* kr = (const float4*)(base + (size_t)tid*(3*H_) + H_ + h*DH_);
        float4* dst = (float4*)&Ks[tid][0];
        #pragma unroll
        for (int i = 0; i < DH_/4; i++) dst[i] = kr[i];
    }
    float q[DH_];
    {
        const float4* qr = (const float4*)(base + (size_t)tid*(3*H_) + h*DH_);
        #pragma unroll
        for (int i = 0; i < DH_/4; i++) ((float4*)q)[i] = qr[i];
    }
    __syncthreads();

    const float scale = 0.17677669529663688110f;   // 1/sqrt(32)
    float m = -INFINITY, l = 0.f;
    float acc[DH_];
    #pragma unroll
    for (int d = 0; d < DH_; d++) acc[d] = 0.f;
    const float* vbase = base + 2*H_ + h*DH_;

    for (int j = 0; j < S_; j++) {
        float s = 0.f;
        #pragma unroll
        for (int d = 0; d < DH_; d++) s = fmaf(q[d], Ks[j][d], s);
        s *= scale;
        float mn = fmaxf(m, s);
        float c  = __expf(m - mn);
        float p  = __expf(s - mn);
        l = l*c + p;
        const float4* vr = (const float4*)(vbase + (size_t)j*(3*H_));
        #pragma unroll
        for (int i = 0; i < DH_/4; i++) {
            float4 vv = vr[i];
            acc[i*4+0] = fmaf(acc[i*4+0], c, p*vv.x);
            acc[i*4+1] = fmaf(acc[i*4+1], c, p*vv.y);
            acc[i*4+2] = fmaf(acc[i*4+2], c, p*vv.z);
            acc[i*4+3] = fmaf(acc[i*4+3], c, p*vv.w);
        }
        m = mn;
    }
    float inv = 1.0f / l;
    float* orow = outp + (size_t)(b*S_ + tid)*H_ + h*DH_;
    #pragma unroll
    for (int d = 0; d < DH_; d++) orow[d] = acc[d]*inv;
}

// ---------------- layernorm: one block (256 threads) per row ----------
__global__ void layernorm_kernel(const float* __restrict__ in,
                                 const float* __restrict__ gw,
                                 const float* __restrict__ gb,
                                 float* __restrict__ outp) {
    __shared__ float red[8];
    __shared__ float s_mean, s_var;
    int row = blockIdx.x, tid = threadIdx.x;
    float v = in[(size_t)row*H_ + tid];
    float s = v;
    #pragma unroll
    for (int o = 16; o > 0; o >>= 1) s += __shfl_xor_sync(0xffffffffu, s, o);
    if ((tid & 31) == 0) red[tid >> 5] = s;
    __syncthreads();
    if (tid == 0) {
        float t = 0.f;
        #pragma unroll
        for (int i = 0; i < 8; i++) t += red[i];
        s_mean = t * (1.0f/H_);
    }
    __syncthreads();
    float mean = s_mean;
    float d = v - mean;
    s = d*d;
    #pragma unroll
    for (int o = 16; o > 0; o >>= 1) s += __shfl_xor_sync(0xffffffffu, s, o);
    if ((tid & 31) == 0) red[tid >> 5] = s;
    __syncthreads();
    if (tid == 0) {
        float t = 0.f;
        #pragma unroll
        for (int i = 0; i < 8; i++) t += red[i];
        s_var = t * (1.0f/H_);
    }
    __syncthreads();
    outp[(size_t)row*H_ + tid] = d * rsqrtf(s_var + 1e-5f) * gw[tid] + gb[tid];
}

// ---------------- head2: logits (M x 13), one thread per output ----------
__global__ void head2_kernel(const float* __restrict__ X,
                             const float* __restrict__ W,
                             const float* __restrict__ bias) {
    int t = blockIdx.x * blockDim.x + threadIdx.x;
    if (t >= B_*S_*NC_) return;
    int row = t / NC_, c = t - row*NC_;
    const float4* x = (const float4*)(X + (size_t)row*H_);
    const float4* w = (const float4*)(W + (size_t)c*H_);
    float s0 = 0.f, s1 = 0.f, s2 = 0.f, s3 = 0.f;
    #pragma unroll 8
    for (int k = 0; k < H_/4; k++) {
        float4 xv = x[k], wv = w[k];
        s0 = fmaf(xv.x, wv.x, s0); s1 = fmaf(xv.y, wv.y, s1);
        s2 = fmaf(xv.z, wv.z, s2); s3 = fmaf(xv.w, wv.w, s3);
    }
    g_logits[t] = (s0+s1) + (s2+s3) + bias[c];
}

// ---------------- final gather to point logits ----------
__global__ void gather_kernel(float* __restrict__ out) {
    int t = blockIdx.x * blockDim.x + threadIdx.x;
    if (t >= B_*N_*NC_) return;
    int r = t / NC_;
    int c = t - r*NC_;
    int b = r >> 15;                // r / N_
    int a = g_assign[r];
    out[t] = g_logits[(b*S_ + a)*NC_ + c];
}

// ---------------- host launcher ----------
extern "C" void kernel_launch(void* const* d_in, const int* in_sizes, int n_in,
                              void* d_out, int out_size) {
    const float* xyz      = (const float*)d_in[0];
    const float* feat     = (const float*)d_in[1];
    const int*   seed_idx = (const int*)  d_in[2];
    const float* proj_w   = (const float*)d_in[3];
    const float* proj_b   = (const float*)d_in[4];
    const float* qkv_w    = (const float*)d_in[5];
    const float* qkv_b    = (const float*)d_in[6];
    const float* out_w    = (const float*)d_in[7];
    const float* out_b    = (const float*)d_in[8];
    const float* ln1_g    = (const float*)d_in[9];
    const float* ln1_b    = (const float*)d_in[10];
    const float* ln2_g    = (const float*)d_in[11];
    const float* ln2_b    = (const float*)d_in[12];
    const float* ff1_w    = (const float*)d_in[13];
    const float* ff1_b    = (const float*)d_in[14];
    const float* ff2_w    = (const float*)d_in[15];
    const float* ff2_b    = (const float*)d_in[16];
    const float* hln_g    = (const float*)d_in[17];
    const float* hln_b    = (const float*)d_in[18];
    const float* h1_w     = (const float*)d_in[19];
    const float* h1_b     = (const float*)d_in[20];
    const float* h2_w     = (const float*)d_in[21];
    const float* h2_b     = (const float*)d_in[22];
    float* out = (float*)d_out;

    float *p_x, *p_qkv, *p_attn, *p_tmp, *p_ff, *p_h1;
    cudaGetSymbolAddress((void**)&p_x,    g_x);
    cudaGetSymbolAddress((void**)&p_qkv,  g_qkv);
    cudaGetSymbolAddress((void**)&p_attn, g_attn);
    cudaGetSymbolAddress((void**)&p_tmp,  g_tmp);
    cudaGetSymbolAddress((void**)&p_ff,   g_ff);
    cudaGetSymbolAddress((void**)&p_h1,   g_h1);

    const int M = B_*S_;   // 4096

    zero_kernel<<<(B_*S_*4 + 255)/256, 256>>>();
    assign_kernel<<<B_*16, 256>>>(xyz, feat, seed_idx);
    tokens_kernel<<<B_*S_, 256>>>(xyz, seed_idx, proj_w, proj_b);

    for (int l = 0; l < 2; l++) {
        // QKV: M=4096, N=768, K=256 -> 128x128 tiles, grid 6x32=192
        sgemm_tc<128,128,64,32,256,2,0><<<dim3(3*H_/128, M/128), 256>>>(
            p_x, qkv_w + (size_t)l*3*H_*H_, qkv_b + l*3*H_, nullptr, p_qkv,
            M, 3*H_, H_);
        attention_kernel<<<B_*NH_, 256>>>(p_qkv, p_attn);
        // out-proj: N=256, K=256 -> 64x64 tiles, grid 4x64=256
        sgemm_tc<64,64,32,32,128,4,2><<<dim3(H_/64, M/64), 128>>>(
            p_attn, out_w + (size_t)l*H_*H_, out_b + l*H_, p_x, p_tmp,
            M, H_, H_);
        layernorm_kernel<<<M, 256>>>(p_tmp, ln1_g + l*H_, ln1_b + l*H_, p_x);
        // FF1: N=1024, K=256 -> 128x128 tiles, grid 8x32=256
        sgemm_tc<128,128,64,32,256,2,1><<<dim3(DFF_/128, M/128), 256>>>(
            p_x, ff1_w + (size_t)l*DFF_*H_, ff1_b + l*DFF_, nullptr, p_ff,
            M, DFF_, H_);
        // FF2: N=256, K=1024 -> 64x64 tiles
        sgemm_tc<64,64,32,32,128,4,2><<<dim3(H_/64, M/64), 128>>>(
            p_ff, ff2_w + (size_t)l*H_*DFF_, ff2_b + l*H_, p_x, p_tmp,
            M, H_, DFF_);
        layernorm_kernel<<<M, 256>>>(p_tmp, ln2_g + l*H_, ln2_b + l*H_, p_x);
    }

    layernorm_kernel<<<M, 256>>>(p_x, hln_g, hln_b, p_tmp);
    sgemm_tc<64,64,32,32,128,4,1><<<dim3(H_/64, M/64), 128>>>(
        p_tmp, h1_w, h1_b, nullptr, p_h1, M, H_, H_);
    head2_kernel<<<(M*NC_ + 255)/256, 256>>>(p_h1, h2_w, h2_b);
    gather_kernel<<<(B_*N_*NC_ + 255)/256, 256>>>(out);
}